// round 1
// baseline (speedup 1.0000x reference)
#include <cuda_runtime.h>
#include <cstddef>

#define NN 50000
#define NE 800000
#define DD 64
#define HH 128

// ---------------- scratch (static device globals; no allocation) ----------------
__device__ float g_sum_src[(size_t)NN * DD];
__device__ float g_sum_dst[(size_t)NN * DD];
__device__ float g_cnt_src[NN];
__device__ float g_cnt_dst[NN];

// ---------------- helpers ----------------
__device__ __forceinline__ float gelu_f(float x) {
    // jax.nn.gelu default (approximate=True):
    // 0.5*x*(1+tanh(sqrt(2/pi)*(x+0.044715 x^3)))
    float u = 0.7978845608028654f * x * (1.0f + 0.044715f * x * x);
    // tanh(u) = 1 - 2/(exp(2u)+1)   (robust at +/- inf)
    float e = __expf(2.0f * u);
    float t = 1.0f - 2.0f / (e + 1.0f);
    return 0.5f * x * (1.0f + t);
}

__device__ __forceinline__ void red_add4(float* p, float a, float b, float c, float d) {
    asm volatile("red.global.add.v4.f32 [%0], {%1, %2, %3, %4};"
                 :: "l"(p), "f"(a), "f"(b), "f"(c), "f"(d) : "memory");
}
__device__ __forceinline__ void red_add1(float* p, float a) {
    asm volatile("red.global.add.f32 [%0], %1;" :: "l"(p), "f"(a) : "memory");
}

// SMEM layout (floats):
//  W1s: 192*128 = 24576
//  W2s: 128*64  =  8192
//  b1s: 128, b2s: 64, gs: 64, bts: 64
//  Xs : 64*192  = 12288   (aliased after GEMM1: Hs = Xs[0:8192], Ys = Xs[8192:12288])
//  eidx: 128 ints (edge kernel only)
#define SMEM_FLOATS (24576 + 8192 + 128 + 64 + 64 + 64 + 12288 + 128)
#define SMEM_BYTES  (SMEM_FLOATS * 4)

// 64-row tile MLP: Xs[64,192] -> GEMM1 -> GELU -> GEMM2 -> Ys[64,64]
// 512 threads: rg = t>>5 (16 row groups of 4 rows), cg = t&31.
__device__ __forceinline__ void mlp_tile(float* __restrict__ Xs,
                                         const float* __restrict__ W1s,
                                         const float* __restrict__ W2s,
                                         const float* __restrict__ b1s,
                                         const float* __restrict__ b2s,
                                         int t) {
    const int rg = t >> 5;
    const int cg = t & 31;
    float* Hs = Xs;            // [64,128]
    float* Ys = Xs + 64 * HH;  // [64,64]

    // ---- GEMM1: [64,192] x [192,128], thread tile 4 rows x 4 cols ----
    float acc[4][4];
#pragma unroll
    for (int j = 0; j < 4; j++) {
        float bv = b1s[cg * 4 + j];
        acc[0][j] = bv; acc[1][j] = bv; acc[2][j] = bv; acc[3][j] = bv;
    }
    const float* xr0 = Xs + (rg * 4 + 0) * 192;
    const float* xr1 = xr0 + 192;
    const float* xr2 = xr1 + 192;
    const float* xr3 = xr2 + 192;
#pragma unroll 4
    for (int k = 0; k < 192; k += 4) {
        float xa[4], xb[4], xc[4], xd[4];
        *(float4*)xa = *(const float4*)(xr0 + k);
        *(float4*)xb = *(const float4*)(xr1 + k);
        *(float4*)xc = *(const float4*)(xr2 + k);
        *(float4*)xd = *(const float4*)(xr3 + k);
#pragma unroll
        for (int kk = 0; kk < 4; kk++) {
            float wv[4];
            *(float4*)wv = *(const float4*)(W1s + (k + kk) * HH + cg * 4);
#pragma unroll
            for (int j = 0; j < 4; j++) {
                acc[0][j] = fmaf(xa[kk], wv[j], acc[0][j]);
                acc[1][j] = fmaf(xb[kk], wv[j], acc[1][j]);
                acc[2][j] = fmaf(xc[kk], wv[j], acc[2][j]);
                acc[3][j] = fmaf(xd[kk], wv[j], acc[3][j]);
            }
        }
    }
    __syncthreads();  // all Xs reads done before Hs (aliased) is written

    // ---- GELU + store H ----
#pragma unroll
    for (int i = 0; i < 4; i++) {
        float hv[4];
#pragma unroll
        for (int j = 0; j < 4; j++) hv[j] = gelu_f(acc[i][j]);
        *(float4*)(Hs + (rg * 4 + i) * HH + cg * 4) = *(float4*)hv;
    }
    __syncthreads();

    // ---- GEMM2: [64,128] x [128,64], thread tile 4 rows x 2 cols ----
    float acc2[4][2];
#pragma unroll
    for (int j = 0; j < 2; j++) {
        float bv = b2s[cg * 2 + j];
        acc2[0][j] = bv; acc2[1][j] = bv; acc2[2][j] = bv; acc2[3][j] = bv;
    }
    const float* hr0 = Hs + (rg * 4 + 0) * HH;
    const float* hr1 = hr0 + HH;
    const float* hr2 = hr1 + HH;
    const float* hr3 = hr2 + HH;
#pragma unroll 4
    for (int k = 0; k < 128; k += 4) {
        float xa[4], xb[4], xc[4], xd[4];
        *(float4*)xa = *(const float4*)(hr0 + k);
        *(float4*)xb = *(const float4*)(hr1 + k);
        *(float4*)xc = *(const float4*)(hr2 + k);
        *(float4*)xd = *(const float4*)(hr3 + k);
#pragma unroll
        for (int kk = 0; kk < 4; kk++) {
            float2 w = *(const float2*)(W2s + (k + kk) * DD + cg * 2);
            acc2[0][0] = fmaf(xa[kk], w.x, acc2[0][0]);
            acc2[0][1] = fmaf(xa[kk], w.y, acc2[0][1]);
            acc2[1][0] = fmaf(xb[kk], w.x, acc2[1][0]);
            acc2[1][1] = fmaf(xb[kk], w.y, acc2[1][1]);
            acc2[2][0] = fmaf(xc[kk], w.x, acc2[2][0]);
            acc2[2][1] = fmaf(xc[kk], w.y, acc2[2][1]);
            acc2[3][0] = fmaf(xd[kk], w.x, acc2[3][0]);
            acc2[3][1] = fmaf(xd[kk], w.y, acc2[3][1]);
        }
    }
#pragma unroll
    for (int i = 0; i < 4; i++)
        *(float2*)(Ys + (rg * 4 + i) * DD + cg * 2) = make_float2(acc2[i][0], acc2[i][1]);
    __syncthreads();  // Ys visible to LN
}

// ---------------- zero scratch ----------------
__global__ void zero_kernel() {
    int idx = blockIdx.x * blockDim.x + threadIdx.x;
    int stride = gridDim.x * blockDim.x;
    for (int i = idx; i < NN * DD; i += stride) { g_sum_src[i] = 0.f; g_sum_dst[i] = 0.f; }
    for (int i = idx; i < NN; i += stride) { g_cnt_src[i] = 0.f; g_cnt_dst[i] = 0.f; }
}

// ---------------- edge kernel ----------------
__global__ __launch_bounds__(512, 1)
void edge_kernel(const float* __restrict__ ndata, const float* __restrict__ edata,
                 const int* __restrict__ src, const int* __restrict__ dst,
                 const float* __restrict__ W1, const float* __restrict__ b1,
                 const float* __restrict__ W2, const float* __restrict__ b2,
                 const float* __restrict__ gam, const float* __restrict__ bet,
                 float* __restrict__ eout, int write_out) {
    extern __shared__ float smem[];
    float* W1s = smem;
    float* W2s = W1s + 192 * HH;
    float* b1s = W2s + HH * DD;
    float* b2s = b1s + 128;
    float* gs  = b2s + 64;
    float* bts = gs + 64;
    float* Xs  = bts + 64;
    int*   eidx = (int*)(Xs + 64 * 192);

    const int t = threadIdx.x;
    for (int i = t; i < 192 * HH; i += 512) W1s[i] = W1[i];
    for (int i = t; i < HH * DD; i += 512) W2s[i] = W2[i];
    if (t < 128) b1s[t] = b1[t];
    if (t < 64) { b2s[t] = b2[t]; gs[t] = gam[t]; bts[t] = bet[t]; }
    __syncthreads();

    const int numTiles = NE / 64;  // 12500, exact
    for (int tile = blockIdx.x; tile < numTiles; tile += gridDim.x) {
        const int e0 = tile * 64;
        if (t < 64) eidx[t] = src[e0 + t];
        else if (t < 128) eidx[t] = dst[e0 + (t - 64)];
        __syncthreads();

        // gather X = [ndata[src] | ndata[dst] | edata]  (64 rows x 48 float4)
        for (int f = t; f < 64 * 48; f += 512) {
            int e = f / 48, p = f % 48;
            float4 v;
            if (p < 16)
                v = *(const float4*)(ndata + (size_t)eidx[e] * DD + p * 4);
            else if (p < 32)
                v = *(const float4*)(ndata + (size_t)eidx[64 + e] * DD + (p - 16) * 4);
            else
                v = *(const float4*)(edata + (size_t)(e0 + e) * DD + (p - 32) * 4);
            *(float4*)(Xs + e * 192 + p * 4) = v;
        }
        __syncthreads();

        mlp_tile(Xs, W1s, W2s, b1s, b2s, t);

        // LayerNorm + output + scatter-add (warp handles 4 rows, in 2 half-warp pairs)
        float* Ys = Xs + 64 * HH;
        const int warp = t >> 5, lane = t & 31;
        const int half = lane >> 4, l16 = lane & 15;
#pragma unroll
        for (int it = 0; it < 2; ++it) {
            int row = warp * 4 + it * 2 + half;
            float ya[4];
            *(float4*)ya = *(const float4*)(Ys + row * DD + l16 * 4);
            float s  = ya[0] + ya[1] + ya[2] + ya[3];
            float ss = ya[0]*ya[0] + ya[1]*ya[1] + ya[2]*ya[2] + ya[3]*ya[3];
#pragma unroll
            for (int o = 8; o; o >>= 1) {
                s  += __shfl_xor_sync(0xffffffffu, s, o);
                ss += __shfl_xor_sync(0xffffffffu, ss, o);
            }
            float mu  = s * (1.0f / 64.0f);
            float var = ss * (1.0f / 64.0f) - mu * mu;
            float rs  = rsqrtf(var + 1e-5f);
            float o4[4];
#pragma unroll
            for (int j = 0; j < 4; j++) {
                int c = l16 * 4 + j;
                o4[j] = (ya[j] - mu) * rs * gs[c] + bts[c];
            }
            if (write_out)
                *(float4*)(eout + (size_t)(e0 + row) * DD + l16 * 4) = *(float4*)o4;
            int sn = eidx[row], dn = eidx[64 + row];
            red_add4(g_sum_src + (size_t)sn * DD + l16 * 4, o4[0], o4[1], o4[2], o4[3]);
            red_add4(g_sum_dst + (size_t)dn * DD + l16 * 4, o4[0], o4[1], o4[2], o4[3]);
            if (l16 == 0) {
                red_add1(g_cnt_src + sn, 1.0f);
                red_add1(g_cnt_dst + dn, 1.0f);
            }
        }
        __syncthreads();  // protect eidx/Xs for next tile
    }
}

// ---------------- node kernel ----------------
__global__ __launch_bounds__(512, 1)
void node_kernel(const float* __restrict__ ndata,
                 const float* __restrict__ W1, const float* __restrict__ b1,
                 const float* __restrict__ W2, const float* __restrict__ b2,
                 const float* __restrict__ gam, const float* __restrict__ bet,
                 float* __restrict__ nout) {
    extern __shared__ float smem[];
    float* W1s = smem;
    float* W2s = W1s + 192 * HH;
    float* b1s = W2s + HH * DD;
    float* b2s = b1s + 128;
    float* gs  = b2s + 64;
    float* bts = gs + 64;
    float* Xs  = bts + 64;

    const int t = threadIdx.x;
    for (int i = t; i < 192 * HH; i += 512) W1s[i] = W1[i];
    for (int i = t; i < HH * DD; i += 512) W2s[i] = W2[i];
    if (t < 128) b1s[t] = b1[t];
    if (t < 64) { b2s[t] = b2[t]; gs[t] = gam[t]; bts[t] = bet[t]; }
    __syncthreads();

    const int numTiles = (NN + 63) / 64;
    for (int tile = blockIdx.x; tile < numTiles; tile += gridDim.x) {
        const int n0 = tile * 64;
        for (int f = t; f < 64 * 48; f += 512) {
            int r = f / 48, p = f % 48;
            int n = n0 + r;
            float4 v = make_float4(0.f, 0.f, 0.f, 0.f);
            if (n < NN) {
                if (p < 16) {
                    float ic = 1.0f / fmaxf(g_cnt_src[n], 1.0f);
                    float4 s4 = *(const float4*)(g_sum_src + (size_t)n * DD + p * 4);
                    v = make_float4(s4.x * ic, s4.y * ic, s4.z * ic, s4.w * ic);
                } else if (p < 32) {
                    float ic = 1.0f / fmaxf(g_cnt_dst[n], 1.0f);
                    float4 s4 = *(const float4*)(g_sum_dst + (size_t)n * DD + (p - 16) * 4);
                    v = make_float4(s4.x * ic, s4.y * ic, s4.z * ic, s4.w * ic);
                } else {
                    v = *(const float4*)(ndata + (size_t)n * DD + (p - 32) * 4);
                }
            }
            *(float4*)(Xs + r * 192 + p * 4) = v;
        }
        __syncthreads();

        mlp_tile(Xs, W1s, W2s, b1s, b2s, t);

        float* Ys = Xs + 64 * HH;
        const int warp = t >> 5, lane = t & 31;
        const int half = lane >> 4, l16 = lane & 15;
#pragma unroll
        for (int it = 0; it < 2; ++it) {
            int row = warp * 4 + it * 2 + half;
            float ya[4];
            *(float4*)ya = *(const float4*)(Ys + row * DD + l16 * 4);
            float s  = ya[0] + ya[1] + ya[2] + ya[3];
            float ss = ya[0]*ya[0] + ya[1]*ya[1] + ya[2]*ya[2] + ya[3]*ya[3];
#pragma unroll
            for (int o = 8; o; o >>= 1) {
                s  += __shfl_xor_sync(0xffffffffu, s, o);
                ss += __shfl_xor_sync(0xffffffffu, ss, o);
            }
            float mu  = s * (1.0f / 64.0f);
            float var = ss * (1.0f / 64.0f) - mu * mu;
            float rs  = rsqrtf(var + 1e-5f);
            int n = n0 + row;
            if (n < NN) {
                float o4[4];
#pragma unroll
                for (int j = 0; j < 4; j++) {
                    int c = l16 * 4 + j;
                    o4[j] = (ya[j] - mu) * rs * gs[c] + bts[c];
                }
                *(float4*)(nout + (size_t)n * DD + l16 * 4) = *(float4*)o4;
            }
        }
        __syncthreads();
    }
}

// ---------------- launch ----------------
extern "C" void kernel_launch(void* const* d_in, const int* in_sizes, int n_in,
                              void* d_out, int out_size) {
    const float* ndata = (const float*)d_in[0];
    const float* edata = (const float*)d_in[1];
    const int*   src   = (const int*)d_in[2];
    const int*   dst   = (const int*)d_in[3];
    const float* eW1 = (const float*)d_in[4];
    const float* eb1 = (const float*)d_in[5];
    const float* eW2 = (const float*)d_in[6];
    const float* eb2 = (const float*)d_in[7];
    const float* eg  = (const float*)d_in[8];
    const float* ebt = (const float*)d_in[9];
    const float* nW1 = (const float*)d_in[10];
    const float* nb1 = (const float*)d_in[11];
    const float* nW2 = (const float*)d_in[12];
    const float* nb2 = (const float*)d_in[13];
    const float* ng  = (const float*)d_in[14];
    const float* nbt = (const float*)d_in[15];

    float* out  = (float*)d_out;
    float* nout = out;                        // ndata_new first (tuple order)
    float* eout = out + (size_t)NN * DD;      // edata_new second
    int write_edges = (out_size >= (NN + NE) * DD) ? 1 : 0;

    int sm = 148;
    cudaDeviceGetAttribute(&sm, cudaDevAttrMultiProcessorCount, 0);

    cudaFuncSetAttribute(edge_kernel, cudaFuncAttributeMaxDynamicSharedMemorySize, SMEM_BYTES);
    cudaFuncSetAttribute(node_kernel, cudaFuncAttributeMaxDynamicSharedMemorySize, SMEM_BYTES);

    zero_kernel<<<1024, 256>>>();
    edge_kernel<<<sm, 512, SMEM_BYTES>>>(ndata, edata, src, dst,
                                         eW1, eb1, eW2, eb2, eg, ebt,
                                         eout, write_edges);
    node_kernel<<<sm, 512, SMEM_BYTES>>>(ndata, nW1, nb1, nW2, nb2, ng, nbt, nout);
}

// round 6
// speedup vs baseline: 1.8747x; 1.8747x over previous
#include <cuda_runtime.h>
#include <cuda_bf16.h>
#include <cstdint>
#include <cstddef>

#define NN 50000
#define NE 800000
#define DD 64
#define HH 128

// padded SMEM strides (in elements)
#define XS  200
#define HS  136
#define W1S 200
#define W2S 136
#define YS  68

// SMEM byte offsets
#define OFF_W1H 0
#define OFF_W1L 51200
#define OFF_W2H 102400
#define OFF_W2L 119808
#define OFF_XH  137216
#define OFF_XL  162816
#define OFF_HH  188416
#define OFF_HL  205824
#define OFF_B1  223232
#define OFF_B2  223744
#define OFF_G   224000
#define OFF_BT  224256
#define OFF_EIX 224512
#define SMEM_BYTES 225024

// ---------------- scratch (static device globals; no allocation) ----------------
__device__ float g_sum_src[(size_t)NN * DD];
__device__ float g_sum_dst[(size_t)NN * DD];
__device__ float g_cnt_src[NN];
__device__ float g_cnt_dst[NN];

// ---------------- helpers ----------------
__device__ __forceinline__ void split_bf16(float x, __nv_bfloat16& h, __nv_bfloat16& l) {
    h = __float2bfloat16(x);
    l = __float2bfloat16(x - __bfloat162float(h));
}

// tanh-GELU, MUFU-free: gelu(x) = x * sigmoid(2u); 2u*log2(e) = x*(2.3021183 + 0.10293917 x^2)
__device__ __forceinline__ float gelu_f(float x) {
    float x2 = x * x;
    float z = x * fmaf(0.10293917f, x2, 2.3021183f);
    z = fminf(fmaxf(z, -30.0f), 30.0f);
    float zi = rintf(z);
    float f = z - zi;
    float p = 0.0013333558f;
    p = fmaf(p, f, 0.0096181291f);
    p = fmaf(p, f, 0.0555041087f);
    p = fmaf(p, f, 0.2402265069f);
    p = fmaf(p, f, 0.6931471806f);
    p = fmaf(p, f, 1.0f);
    int ii = (int)zi;
    float E = __int_as_float(__float_as_int(p) + (ii << 23));
    float d = 1.0f + E;
    float r = __int_as_float(0x7EF311C3u - (unsigned)__float_as_int(d));
    r = r * (2.0f - d * r);
    r = r * (2.0f - d * r);
    r = r * (2.0f - d * r);          // r = 1/(1+E)
    return x * (1.0f - r);           // x * E/(1+E)
}

__device__ __forceinline__ void red_add4(float* p, float a, float b, float c, float d) {
    asm volatile("red.global.add.v4.f32 [%0], {%1, %2, %3, %4};"
                 :: "l"(p), "f"(a), "f"(b), "f"(c), "f"(d) : "memory");
}
__device__ __forceinline__ void red_add1(float* p, float a) {
    asm volatile("red.global.add.f32 [%0], %1;" :: "l"(p), "f"(a) : "memory");
}

__device__ __forceinline__ void mma_bf16(float (&c)[4],
                                         uint32_t a0, uint32_t a1, uint32_t a2, uint32_t a3,
                                         uint32_t b0, uint32_t b1) {
    asm volatile("mma.sync.aligned.m16n8k16.row.col.f32.bf16.bf16.f32 "
                 "{%0,%1,%2,%3}, {%4,%5,%6,%7}, {%8,%9}, {%0,%1,%2,%3};"
                 : "+f"(c[0]), "+f"(c[1]), "+f"(c[2]), "+f"(c[3])
                 : "r"(a0), "r"(a1), "r"(a2), "r"(a3), "r"(b0), "r"(b1));
}

// ---------------- shared weight/bias load + decompose (512 threads) ----------------
__device__ __forceinline__ void load_weights(char* smem,
                                             const float* __restrict__ W1, const float* __restrict__ b1,
                                             const float* __restrict__ W2, const float* __restrict__ b2,
                                             const float* __restrict__ gam, const float* __restrict__ bet,
                                             int t) {
    __nv_bfloat16* W1h = (__nv_bfloat16*)(smem + OFF_W1H);
    __nv_bfloat16* W1l = (__nv_bfloat16*)(smem + OFF_W1L);
    __nv_bfloat16* W2h = (__nv_bfloat16*)(smem + OFF_W2H);
    __nv_bfloat16* W2l = (__nv_bfloat16*)(smem + OFF_W2L);
    float* b1s = (float*)(smem + OFF_B1);
    float* b2s = (float*)(smem + OFF_B2);
    float* gs  = (float*)(smem + OFF_G);
    float* bts = (float*)(smem + OFF_BT);

    for (int i = t; i < 192 * HH; i += 512) {
        int k = i >> 7, n = i & 127;
        __nv_bfloat16 h, l;
        split_bf16(W1[i], h, l);           // W1[k*128+n]
        W1h[n * W1S + k] = h;
        W1l[n * W1S + k] = l;
    }
    for (int i = t; i < HH * DD; i += 512) {
        int k = i >> 6, n = i & 63;
        __nv_bfloat16 h, l;
        split_bf16(W2[i], h, l);
        W2h[n * W2S + k] = h;
        W2l[n * W2S + k] = l;
    }
    if (t < 128) b1s[t] = b1[t];
    if (t < 64) { b2s[t] = b2[t]; gs[t] = gam[t]; bts[t] = bet[t]; }
}

// ---------------- 64-row tile MLP on tensor cores (512 threads / 16 warps) ----------------
// Warp w: rows m0 = (w>>2)*16. GEMM1 cols n0 = (w&3)*32 (4 x 8). GEMM2 cols n0 = (w&3)*16 (2 x 8).
__device__ __forceinline__ void mlp_tile_tc(char* smem, int t) {
    const __nv_bfloat16* W1h = (const __nv_bfloat16*)(smem + OFF_W1H);
    const __nv_bfloat16* W1l = (const __nv_bfloat16*)(smem + OFF_W1L);
    const __nv_bfloat16* W2h = (const __nv_bfloat16*)(smem + OFF_W2H);
    const __nv_bfloat16* W2l = (const __nv_bfloat16*)(smem + OFF_W2L);
    const __nv_bfloat16* Xh  = (const __nv_bfloat16*)(smem + OFF_XH);
    const __nv_bfloat16* Xl  = (const __nv_bfloat16*)(smem + OFF_XL);
    __nv_bfloat16* Hh = (__nv_bfloat16*)(smem + OFF_HH);
    __nv_bfloat16* Hl = (__nv_bfloat16*)(smem + OFF_HL);
    float* Ys = (float*)(smem + OFF_XH);   // alias: X dead after GEMM1 sync
    const float* b1s = (const float*)(smem + OFF_B1);
    const float* b2s = (const float*)(smem + OFF_B2);

    const int warp = t >> 5, lane = t & 31;
    const int g = lane >> 2, tg = lane & 3;
    const int m0 = (warp >> 2) * 16;

    // ---------------- GEMM1: [64,192]x[192,128] ----------------
    {
        const int n0 = (warp & 3) * 32;
        float C[4][4];
#pragma unroll
        for (int nt = 0; nt < 4; nt++) {
            float bv0 = b1s[n0 + nt * 8 + 2 * tg];
            float bv1 = b1s[n0 + nt * 8 + 2 * tg + 1];
            C[nt][0] = bv0; C[nt][1] = bv1; C[nt][2] = bv0; C[nt][3] = bv1;
        }
        const __nv_bfloat16* xr0h = Xh + (m0 + g) * XS;
        const __nv_bfloat16* xr8h = xr0h + 8 * XS;
        const __nv_bfloat16* xr0l = Xl + (m0 + g) * XS;
        const __nv_bfloat16* xr8l = xr0l + 8 * XS;
#pragma unroll
        for (int ks = 0; ks < 12; ks++) {
            const int k0 = ks * 16 + 2 * tg;
            uint32_t ah0 = *(const uint32_t*)(xr0h + k0);
            uint32_t ah1 = *(const uint32_t*)(xr8h + k0);
            uint32_t ah2 = *(const uint32_t*)(xr0h + k0 + 8);
            uint32_t ah3 = *(const uint32_t*)(xr8h + k0 + 8);
            uint32_t al0 = *(const uint32_t*)(xr0l + k0);
            uint32_t al1 = *(const uint32_t*)(xr8l + k0);
            uint32_t al2 = *(const uint32_t*)(xr0l + k0 + 8);
            uint32_t al3 = *(const uint32_t*)(xr8l + k0 + 8);
#pragma unroll
            for (int nt = 0; nt < 4; nt++) {
                const __nv_bfloat16* wh = W1h + (n0 + nt * 8 + g) * W1S + k0;
                const __nv_bfloat16* wl = W1l + (n0 + nt * 8 + g) * W1S + k0;
                uint32_t bh0 = *(const uint32_t*)(wh);
                uint32_t bh1 = *(const uint32_t*)(wh + 8);
                uint32_t bl0 = *(const uint32_t*)(wl);
                uint32_t bl1 = *(const uint32_t*)(wl + 8);
                mma_bf16(C[nt], ah0, ah1, ah2, ah3, bh0, bh1);
                mma_bf16(C[nt], ah0, ah1, ah2, ah3, bl0, bl1);
                mma_bf16(C[nt], al0, al1, al2, al3, bh0, bh1);
            }
        }
        // GELU + decompose + store H
#pragma unroll
        for (int nt = 0; nt < 4; nt++) {
            const int col = n0 + nt * 8 + 2 * tg;
            float y0 = gelu_f(C[nt][0]);
            float y1 = gelu_f(C[nt][1]);
            float y2 = gelu_f(C[nt][2]);
            float y3 = gelu_f(C[nt][3]);
            __nv_bfloat16 h0, l0, h1, l1, h2, l2, h3, l3;
            split_bf16(y0, h0, l0); split_bf16(y1, h1, l1);
            split_bf16(y2, h2, l2); split_bf16(y3, h3, l3);
            __nv_bfloat162 vh0; vh0.x = h0; vh0.y = h1;
            __nv_bfloat162 vh1; vh1.x = h2; vh1.y = h3;
            __nv_bfloat162 vl0; vl0.x = l0; vl0.y = l1;
            __nv_bfloat162 vl1; vl1.x = l2; vl1.y = l3;
            *(__nv_bfloat162*)(Hh + (m0 + g) * HS + col)     = vh0;
            *(__nv_bfloat162*)(Hh + (m0 + g + 8) * HS + col) = vh1;
            *(__nv_bfloat162*)(Hl + (m0 + g) * HS + col)     = vl0;
            *(__nv_bfloat162*)(Hl + (m0 + g + 8) * HS + col) = vl1;
        }
    }
    __syncthreads();   // H complete; X reads done (Y alias safe)

    // ---------------- GEMM2: [64,128]x[128,64] ----------------
    {
        const int n0 = (warp & 3) * 16;
        float C[2][4];
#pragma unroll
        for (int nt = 0; nt < 2; nt++) {
            float bv0 = b2s[n0 + nt * 8 + 2 * tg];
            float bv1 = b2s[n0 + nt * 8 + 2 * tg + 1];
            C[nt][0] = bv0; C[nt][1] = bv1; C[nt][2] = bv0; C[nt][3] = bv1;
        }
        const __nv_bfloat16* hr0h = Hh + (m0 + g) * HS;
        const __nv_bfloat16* hr8h = hr0h + 8 * HS;
        const __nv_bfloat16* hr0l = Hl + (m0 + g) * HS;
        const __nv_bfloat16* hr8l = hr0l + 8 * HS;
#pragma unroll
        for (int ks = 0; ks < 8; ks++) {
            const int k0 = ks * 16 + 2 * tg;
            uint32_t ah0 = *(const uint32_t*)(hr0h + k0);
            uint32_t ah1 = *(const uint32_t*)(hr8h + k0);
            uint32_t ah2 = *(const uint32_t*)(hr0h + k0 + 8);
            uint32_t ah3 = *(const uint32_t*)(hr8h + k0 + 8);
            uint32_t al0 = *(const uint32_t*)(hr0l + k0);
            uint32_t al1 = *(const uint32_t*)(hr8l + k0);
            uint32_t al2 = *(const uint32_t*)(hr0l + k0 + 8);
            uint32_t al3 = *(const uint32_t*)(hr8l + k0 + 8);
#pragma unroll
            for (int nt = 0; nt < 2; nt++) {
                const __nv_bfloat16* wh = W2h + (n0 + nt * 8 + g) * W2S + k0;
                const __nv_bfloat16* wl = W2l + (n0 + nt * 8 + g) * W2S + k0;
                uint32_t bh0 = *(const uint32_t*)(wh);
                uint32_t bh1 = *(const uint32_t*)(wh + 8);
                uint32_t bl0 = *(const uint32_t*)(wl);
                uint32_t bl1 = *(const uint32_t*)(wl + 8);
                mma_bf16(C[nt], ah0, ah1, ah2, ah3, bh0, bh1);
                mma_bf16(C[nt], ah0, ah1, ah2, ah3, bl0, bl1);
                mma_bf16(C[nt], al0, al1, al2, al3, bh0, bh1);
            }
        }
#pragma unroll
        for (int nt = 0; nt < 2; nt++) {
            const int col = n0 + nt * 8 + 2 * tg;
            *(float2*)(Ys + (m0 + g) * YS + col)     = make_float2(C[nt][0], C[nt][1]);
            *(float2*)(Ys + (m0 + g + 8) * YS + col) = make_float2(C[nt][2], C[nt][3]);
        }
    }
    __syncthreads();   // Y visible to LN
}

// ---------------- zero scratch ----------------
__global__ void zero_kernel() {
    int idx = blockIdx.x * blockDim.x + threadIdx.x;
    int stride = gridDim.x * blockDim.x;
    for (int i = idx; i < NN * DD; i += stride) { g_sum_src[i] = 0.f; g_sum_dst[i] = 0.f; }
    for (int i = idx; i < NN; i += stride) { g_cnt_src[i] = 0.f; g_cnt_dst[i] = 0.f; }
}

// ---------------- edge kernel ----------------
__global__ __launch_bounds__(512, 1)
void edge_kernel(const float* __restrict__ ndata, const float* __restrict__ edata,
                 const int* __restrict__ src, const int* __restrict__ dst,
                 const float* __restrict__ W1, const float* __restrict__ b1,
                 const float* __restrict__ W2, const float* __restrict__ b2,
                 const float* __restrict__ gam, const float* __restrict__ bet,
                 float* __restrict__ eout, int write_out) {
    extern __shared__ char smem[];
    const int t = threadIdx.x;
    load_weights(smem, W1, b1, W2, b2, gam, bet, t);

    __nv_bfloat16* Xh = (__nv_bfloat16*)(smem + OFF_XH);
    __nv_bfloat16* Xl = (__nv_bfloat16*)(smem + OFF_XL);
    float* Ys  = (float*)(smem + OFF_XH);
    const float* gs  = (const float*)(smem + OFF_G);
    const float* bts = (const float*)(smem + OFF_BT);
    int* eidx = (int*)(smem + OFF_EIX);
    __syncthreads();

    const int numTiles = NE / 64;  // 12500
    for (int tile = blockIdx.x; tile < numTiles; tile += gridDim.x) {
        const int e0 = tile * 64;
        if (t < 64) eidx[t] = src[e0 + t];
        else if (t < 128) eidx[t] = dst[e0 + (t - 64)];
        __syncthreads();

        // gather X = [ndata[src] | ndata[dst] | edata] -> bf16 hi/lo
        for (int f = t; f < 64 * 48; f += 512) {
            int e = f / 48, p = f % 48;
            float4 v;
            if (p < 16)
                v = *(const float4*)(ndata + (size_t)eidx[e] * DD + p * 4);
            else if (p < 32)
                v = *(const float4*)(ndata + (size_t)eidx[64 + e] * DD + (p - 16) * 4);
            else
                v = *(const float4*)(edata + (size_t)(e0 + e) * DD + (p - 32) * 4);
            __nv_bfloat16 h0, l0, h1, l1, h2, l2, h3, l3;
            split_bf16(v.x, h0, l0); split_bf16(v.y, h1, l1);
            split_bf16(v.z, h2, l2); split_bf16(v.w, h3, l3);
            __nv_bfloat162 a; a.x = h0; a.y = h1;
            __nv_bfloat162 b; b.x = h2; b.y = h3;
            __nv_bfloat162 c; c.x = l0; c.y = l1;
            __nv_bfloat162 d; d.x = l2; d.y = l3;
            *(__nv_bfloat162*)(Xh + e * XS + p * 4)     = a;
            *(__nv_bfloat162*)(Xh + e * XS + p * 4 + 2) = b;
            *(__nv_bfloat162*)(Xl + e * XS + p * 4)     = c;
            *(__nv_bfloat162*)(Xl + e * XS + p * 4 + 2) = d;
        }
        __syncthreads();

        mlp_tile_tc(smem, t);

        // LayerNorm + output + scatter (16 warps x 4 rows, half-warp per row)
        const int warp = t >> 5, lane = t & 31;
        const int half = lane >> 4, l16 = lane & 15;
#pragma unroll
        for (int it = 0; it < 2; ++it) {
            int row = warp * 4 + it * 2 + half;
            float ya[4];
            *(float4*)ya = *(const float4*)(Ys + row * YS + l16 * 4);
            float s  = ya[0] + ya[1] + ya[2] + ya[3];
            float ss = ya[0]*ya[0] + ya[1]*ya[1] + ya[2]*ya[2] + ya[3]*ya[3];
#pragma unroll
            for (int o = 8; o; o >>= 1) {
                s  += __shfl_xor_sync(0xffffffffu, s, o);
                ss += __shfl_xor_sync(0xffffffffu, ss, o);
            }
            float mu  = s * (1.0f / 64.0f);
            float var = ss * (1.0f / 64.0f) - mu * mu;
            float rs  = rsqrtf(var + 1e-5f);
            float o4[4];
#pragma unroll
            for (int j = 0; j < 4; j++) {
                int c = l16 * 4 + j;
                o4[j] = (ya[j] - mu) * rs * gs[c] + bts[c];
            }
            if (write_out)
                *(float4*)(eout + (size_t)(e0 + row) * DD + l16 * 4) = *(float4*)o4;
            int sn = eidx[row], dn = eidx[64 + row];
            red_add4(g_sum_src + (size_t)sn * DD + l16 * 4, o4[0], o4[1], o4[2], o4[3]);
            red_add4(g_sum_dst + (size_t)dn * DD + l16 * 4, o4[0], o4[1], o4[2], o4[3]);
            if (l16 == 0) {
                red_add1(g_cnt_src + sn, 1.0f);
                red_add1(g_cnt_dst + dn, 1.0f);
            }
        }
        __syncthreads();  // protect eidx/X for next tile
    }
}

// ---------------- node kernel ----------------
__global__ __launch_bounds__(512, 1)
void node_kernel(const float* __restrict__ ndata,
                 const float* __restrict__ W1, const float* __restrict__ b1,
                 const float* __restrict__ W2, const float* __restrict__ b2,
                 const float* __restrict__ gam, const float* __restrict__ bet,
                 float* __restrict__ nout) {
    extern __shared__ char smem[];
    const int t = threadIdx.x;
    load_weights(smem, W1, b1, W2, b2, gam, bet, t);

    __nv_bfloat16* Xh = (__nv_bfloat16*)(smem + OFF_XH);
    __nv_bfloat16* Xl = (__nv_bfloat16*)(smem + OFF_XL);
    float* Ys  = (float*)(smem + OFF_XH);
    const float* gs  = (const float*)(smem + OFF_G);
    const float* bts = (const float*)(smem + OFF_BT);
    __syncthreads();

    const int numTiles = (NN + 63) / 64;
    for (int tile = blockIdx.x; tile < numTiles; tile += gridDim.x) {
        const int n0 = tile * 64;
        for (int f = t; f < 64 * 48; f += 512) {
            int r = f / 48, p = f % 48;
            int n = n0 + r;
            float4 v = make_float4(0.f, 0.f, 0.f, 0.f);
            if (n < NN) {
                if (p < 16) {
                    float ic = 1.0f / fmaxf(g_cnt_src[n], 1.0f);
                    float4 s4 = *(const float4*)(g_sum_src + (size_t)n * DD + p * 4);
                    v = make_float4(s4.x * ic, s4.y * ic, s4.z * ic, s4.w * ic);
                } else if (p < 32) {
                    float ic = 1.0f / fmaxf(g_cnt_dst[n], 1.0f);
                    float4 s4 = *(const float4*)(g_sum_dst + (size_t)n * DD + (p - 16) * 4);
                    v = make_float4(s4.x * ic, s4.y * ic, s4.z * ic, s4.w * ic);
                } else {
                    v = *(const float4*)(ndata + (size_t)n * DD + (p - 32) * 4);
                }
            }
            __nv_bfloat16 h0, l0, h1, l1, h2, l2, h3, l3;
            split_bf16(v.x, h0, l0); split_bf16(v.y, h1, l1);
            split_bf16(v.z, h2, l2); split_bf16(v.w, h3, l3);
            __nv_bfloat162 a; a.x = h0; a.y = h1;
            __nv_bfloat162 b; b.x = h2; b.y = h3;
            __nv_bfloat162 c; c.x = l0; c.y = l1;
            __nv_bfloat162 d; d.x = l2; d.y = l3;
            *(__nv_bfloat162*)(Xh + r * XS + p * 4)     = a;
            *(__nv_bfloat162*)(Xh + r * XS + p * 4 + 2) = b;
            *(__nv_bfloat162*)(Xl + r * XS + p * 4)     = c;
            *(__nv_bfloat162*)(Xl + r * XS + p * 4 + 2) = d;
        }
        __syncthreads();

        mlp_tile_tc(smem, t);

        const int warp = t >> 5, lane = t & 31;
        const int half = lane >> 4, l16 = lane & 15;
#pragma unroll
        for (int it = 0; it < 2; ++it) {
            int row = warp * 4 + it * 2 + half;
            float ya[4];
            *(float4*)ya = *(const float4*)(Ys + row * YS + l16 * 4);
            float s  = ya[0] + ya[1] + ya[2] + ya[3];
            float ss = ya[0]*ya[0] + ya[1]*ya[1] + ya[2]*ya[2] + ya[3]*ya[3];
#pragma unroll
            for (int o = 8; o; o >>= 1) {
                s  += __shfl_xor_sync(0xffffffffu, s, o);
                ss += __shfl_xor_sync(0xffffffffu, ss, o);
            }
            float mu  = s * (1.0f / 64.0f);
            float var = ss * (1.0f / 64.0f) - mu * mu;
            float rs  = rsqrtf(var + 1e-5f);
            int n = n0 + row;
            if (n < NN) {
                float o4[4];
#pragma unroll
                for (int j = 0; j < 4; j++) {
                    int c = l16 * 4 + j;
                    o4[j] = (ya[j] - mu) * rs * gs[c] + bts[c];
                }
                *(float4*)(nout + (size_t)n * DD + l16 * 4) = *(float4*)o4;
            }
        }
        __syncthreads();
    }
}

// ---------------- launch ----------------
extern "C" void kernel_launch(void* const* d_in, const int* in_sizes, int n_in,
                              void* d_out, int out_size) {
    const float* ndata = (const float*)d_in[0];
    const float* edata = (const float*)d_in[1];
    const int*   src   = (const int*)d_in[2];
    const int*   dst   = (const int*)d_in[3];
    const float* eW1 = (const float*)d_in[4];
    const float* eb1 = (const float*)d_in[5];
    const float* eW2 = (const float*)d_in[6];
    const float* eb2 = (const float*)d_in[7];
    const float* eg  = (const float*)d_in[8];
    const float* ebt = (const float*)d_in[9];
    const float* nW1 = (const float*)d_in[10];
    const float* nb1 = (const float*)d_in[11];
    const float* nW2 = (const float*)d_in[12];
    const float* nb2 = (const float*)d_in[13];
    const float* ng  = (const float*)d_in[14];
    const float* nbt = (const float*)d_in[15];

    float* out  = (float*)d_out;
    float* nout = out;                        // ndata_new first
    float* eout = out + (size_t)NN * DD;      // edata_new second
    int write_edges = (out_size >= (NN + NE) * DD) ? 1 : 0;

    int sm = 148;
    cudaDeviceGetAttribute(&sm, cudaDevAttrMultiProcessorCount, 0);

    cudaFuncSetAttribute(edge_kernel, cudaFuncAttributeMaxDynamicSharedMemorySize, SMEM_BYTES);
    cudaFuncSetAttribute(node_kernel, cudaFuncAttributeMaxDynamicSharedMemorySize, SMEM_BYTES);

    zero_kernel<<<1024, 256>>>();
    edge_kernel<<<sm, 512, SMEM_BYTES>>>(ndata, edata, src, dst,
                                         eW1, eb1, eW2, eb2, eg, ebt,
                                         eout, write_edges);
    node_kernel<<<sm, 512, SMEM_BYTES>>>(ndata, nW1, nb1, nW2, nb2, ng, nbt, nout);
}

// round 7
// speedup vs baseline: 2.3973x; 1.2788x over previous
#include <cuda_runtime.h>
#include <cuda_bf16.h>
#include <cstdint>
#include <cstddef>

#define NN 50000
#define NE 800000
#define DD 64
#define HH 128

// padded SMEM strides (in elements); all strides*2B mod 128B == 16B -> ldmatrix conflict-free
#define XS  200
#define HS  136
#define W1S 200
#define W2S 136
#define YS  68

// SMEM byte offsets
#define OFF_W1H 0
#define OFF_W1L 51200
#define OFF_W2H 102400
#define OFF_W2L 119808
#define OFF_XH  137216
#define OFF_XL  162816
#define OFF_HH  188416
#define OFF_HL  205824
#define OFF_B1  223232
#define OFF_B2  223744
#define OFF_G   224000
#define OFF_BT  224256
#define OFF_EIX 224512
#define SMEM_BYTES 225536   // includes 2x128 int eidx double buffer

// ---------------- scratch (static device globals; no allocation) ----------------
__device__ float g_sum_src[(size_t)NN * DD];
__device__ float g_sum_dst[(size_t)NN * DD];
__device__ float g_cnt_src[NN];
__device__ float g_cnt_dst[NN];

// ---------------- helpers ----------------
__device__ __forceinline__ void split_bf16(float x, __nv_bfloat16& h, __nv_bfloat16& l) {
    h = __float2bfloat16(x);
    l = __float2bfloat16(x - __bfloat162float(h));
}

// tanh-GELU, MUFU-free
__device__ __forceinline__ float gelu_f(float x) {
    float x2 = x * x;
    float z = x * fmaf(0.10293917f, x2, 2.3021183f);
    z = fminf(fmaxf(z, -30.0f), 30.0f);
    float zi = rintf(z);
    float f = z - zi;
    float p = 0.0013333558f;
    p = fmaf(p, f, 0.0096181291f);
    p = fmaf(p, f, 0.0555041087f);
    p = fmaf(p, f, 0.2402265069f);
    p = fmaf(p, f, 0.6931471806f);
    p = fmaf(p, f, 1.0f);
    int ii = (int)zi;
    float E = __int_as_float(__float_as_int(p) + (ii << 23));
    float d = 1.0f + E;
    float r = __int_as_float(0x7EF311C3u - (unsigned)__float_as_int(d));
    r = r * (2.0f - d * r);
    r = r * (2.0f - d * r);
    r = r * (2.0f - d * r);          // r = 1/(1+E)
    return x * (1.0f - r);           // x * E/(1+E)
}

__device__ __forceinline__ void red_add4(float* p, float a, float b, float c, float d) {
    asm volatile("red.global.add.v4.f32 [%0], {%1, %2, %3, %4};"
                 :: "l"(p), "f"(a), "f"(b), "f"(c), "f"(d) : "memory");
}
__device__ __forceinline__ void red_add1(float* p, float a) {
    asm volatile("red.global.add.f32 [%0], %1;" :: "l"(p), "f"(a) : "memory");
}

__device__ __forceinline__ void mma_bf16(float (&c)[4],
                                         uint32_t a0, uint32_t a1, uint32_t a2, uint32_t a3,
                                         uint32_t b0, uint32_t b1) {
    asm volatile("mma.sync.aligned.m16n8k16.row.col.f32.bf16.bf16.f32 "
                 "{%0,%1,%2,%3}, {%4,%5,%6,%7}, {%8,%9}, {%0,%1,%2,%3};"
                 : "+f"(c[0]), "+f"(c[1]), "+f"(c[2]), "+f"(c[3])
                 : "r"(a0), "r"(a1), "r"(a2), "r"(a3), "r"(b0), "r"(b1));
}

__device__ __forceinline__ void ldsm4(uint32_t& r0, uint32_t& r1, uint32_t& r2, uint32_t& r3,
                                      uint32_t a) {
    asm volatile("ldmatrix.sync.aligned.m8n8.x4.shared.b16 {%0,%1,%2,%3}, [%4];"
                 : "=r"(r0), "=r"(r1), "=r"(r2), "=r"(r3) : "r"(a));
}

__device__ __forceinline__ uint32_t smem_u32(const void* p) {
    return (uint32_t)__cvta_generic_to_shared(p);
}

// ---------------- shared weight/bias load + decompose (512 threads) ----------------
__device__ __forceinline__ void load_weights(char* smem,
                                             const float* __restrict__ W1, const float* __restrict__ b1,
                                             const float* __restrict__ W2, const float* __restrict__ b2,
                                             const float* __restrict__ gam, const float* __restrict__ bet,
                                             int t) {
    __nv_bfloat16* W1h = (__nv_bfloat16*)(smem + OFF_W1H);
    __nv_bfloat16* W1l = (__nv_bfloat16*)(smem + OFF_W1L);
    __nv_bfloat16* W2h = (__nv_bfloat16*)(smem + OFF_W2H);
    __nv_bfloat16* W2l = (__nv_bfloat16*)(smem + OFF_W2L);
    float* b1s = (float*)(smem + OFF_B1);
    float* b2s = (float*)(smem + OFF_B2);
    float* gs  = (float*)(smem + OFF_G);
    float* bts = (float*)(smem + OFF_BT);

    for (int i = t; i < 192 * HH; i += 512) {
        int k = i >> 7, n = i & 127;
        __nv_bfloat16 h, l;
        split_bf16(W1[i], h, l);           // W1[k*128+n] -> transposed [n][k]
        W1h[n * W1S + k] = h;
        W1l[n * W1S + k] = l;
    }
    for (int i = t; i < HH * DD; i += 512) {
        int k = i >> 6, n = i & 63;
        __nv_bfloat16 h, l;
        split_bf16(W2[i], h, l);
        W2h[n * W2S + k] = h;
        W2l[n * W2S + k] = l;
    }
    if (t < 128) b1s[t] = b1[t];
    if (t < 64) { b2s[t] = b2[t]; gs[t] = gam[t]; bts[t] = bet[t]; }
}

// ---------------- store one gathered float4 as bf16 hi/lo into X ----------------
__device__ __forceinline__ void store_x(__nv_bfloat16* Xh, __nv_bfloat16* Xl,
                                        int e, int p, float4 v) {
    __nv_bfloat16 h0, l0, h1, l1, h2, l2, h3, l3;
    split_bf16(v.x, h0, l0); split_bf16(v.y, h1, l1);
    split_bf16(v.z, h2, l2); split_bf16(v.w, h3, l3);
    __nv_bfloat162 a; a.x = h0; a.y = h1;
    __nv_bfloat162 b; b.x = h2; b.y = h3;
    __nv_bfloat162 c; c.x = l0; c.y = l1;
    __nv_bfloat162 d; d.x = l2; d.y = l3;
    *(__nv_bfloat162*)(Xh + e * XS + p * 4)     = a;
    *(__nv_bfloat162*)(Xh + e * XS + p * 4 + 2) = b;
    *(__nv_bfloat162*)(Xl + e * XS + p * 4)     = c;
    *(__nv_bfloat162*)(Xl + e * XS + p * 4 + 2) = d;
}

// ---------------- 64-row tile MLP on tensor cores (512 threads / 16 warps) ----------------
// All fragment loads via ldmatrix.x4 (conflict-free: row strides mod 128B == 16B).
__device__ __forceinline__ void mlp_tile_tc(char* smem, int t) {
    const __nv_bfloat16* W1h = (const __nv_bfloat16*)(smem + OFF_W1H);
    const __nv_bfloat16* W1l = (const __nv_bfloat16*)(smem + OFF_W1L);
    const __nv_bfloat16* W2h = (const __nv_bfloat16*)(smem + OFF_W2H);
    const __nv_bfloat16* W2l = (const __nv_bfloat16*)(smem + OFF_W2L);
    const __nv_bfloat16* Xh  = (const __nv_bfloat16*)(smem + OFF_XH);
    const __nv_bfloat16* Xl  = (const __nv_bfloat16*)(smem + OFF_XL);
    __nv_bfloat16* Hh = (__nv_bfloat16*)(smem + OFF_HH);
    __nv_bfloat16* Hl = (__nv_bfloat16*)(smem + OFF_HL);
    float* Ys = (float*)(smem + OFF_XH);   // alias: X dead after GEMM1 sync
    const float* b1s = (const float*)(smem + OFF_B1);
    const float* b2s = (const float*)(smem + OFF_B2);

    const int warp = t >> 5, lane = t & 31;
    const int g = lane >> 2, tg = lane & 3;
    const int m0 = (warp >> 2) * 16;
    // ldmatrix lane roles
    const int lrow = lane & 15;            // A: row within 16
    const int akh  = (lane >> 4) & 1;      // A: k-half
    const int brow = lane & 7;             // B: row within 8
    const int bkh  = (lane >> 3) & 1;      // B: k-half (matrix&1)
    const int bnt  = (lane >> 4) & 1;      // B: nt within pair (matrix>>1)

    // ---------------- GEMM1: [64,192]x[192,128] ----------------
    {
        const int n0 = (warp & 3) * 32;
        float C[4][4];
#pragma unroll
        for (int nt = 0; nt < 4; nt++) {
            float bv0 = b1s[n0 + nt * 8 + 2 * tg];
            float bv1 = b1s[n0 + nt * 8 + 2 * tg + 1];
            C[nt][0] = bv0; C[nt][1] = bv1; C[nt][2] = bv0; C[nt][3] = bv1;
        }
        uint32_t aXh = smem_u32(Xh + (m0 + lrow) * XS) + akh * 16;
        uint32_t aXl = smem_u32(Xl + (m0 + lrow) * XS) + akh * 16;
        uint32_t bHp0 = smem_u32(W1h + (n0 + (0 + bnt) * 8 + brow) * W1S) + bkh * 16;
        uint32_t bHp1 = smem_u32(W1h + (n0 + (2 + bnt) * 8 + brow) * W1S) + bkh * 16;
        uint32_t bLp0 = smem_u32(W1l + (n0 + (0 + bnt) * 8 + brow) * W1S) + bkh * 16;
        uint32_t bLp1 = smem_u32(W1l + (n0 + (2 + bnt) * 8 + brow) * W1S) + bkh * 16;
#pragma unroll
        for (int ks = 0; ks < 12; ks++) {
            const uint32_t off = ks * 32;
            uint32_t ah0, ah1, ah2, ah3, al0, al1, al2, al3;
            ldsm4(ah0, ah1, ah2, ah3, aXh + off);
            ldsm4(al0, al1, al2, al3, aXl + off);
            uint32_t p00, p01, p10, p11;   // W1h: nt0 {b0,b1}, nt1 {b0,b1}
            ldsm4(p00, p01, p10, p11, bHp0 + off);
            uint32_t q00, q01, q10, q11;   // W1l
            ldsm4(q00, q01, q10, q11, bLp0 + off);
            mma_bf16(C[0], ah0, ah1, ah2, ah3, p00, p01);
            mma_bf16(C[0], ah0, ah1, ah2, ah3, q00, q01);
            mma_bf16(C[0], al0, al1, al2, al3, p00, p01);
            mma_bf16(C[1], ah0, ah1, ah2, ah3, p10, p11);
            mma_bf16(C[1], ah0, ah1, ah2, ah3, q10, q11);
            mma_bf16(C[1], al0, al1, al2, al3, p10, p11);
            uint32_t r00, r01, r10, r11;
            ldsm4(r00, r01, r10, r11, bHp1 + off);
            uint32_t s00, s01, s10, s11;
            ldsm4(s00, s01, s10, s11, bLp1 + off);
            mma_bf16(C[2], ah0, ah1, ah2, ah3, r00, r01);
            mma_bf16(C[2], ah0, ah1, ah2, ah3, s00, s01);
            mma_bf16(C[2], al0, al1, al2, al3, r00, r01);
            mma_bf16(C[3], ah0, ah1, ah2, ah3, r10, r11);
            mma_bf16(C[3], ah0, ah1, ah2, ah3, s10, s11);
            mma_bf16(C[3], al0, al1, al2, al3, r10, r11);
        }
        // GELU + decompose + store H
#pragma unroll
        for (int nt = 0; nt < 4; nt++) {
            const int col = n0 + nt * 8 + 2 * tg;
            float y0 = gelu_f(C[nt][0]);
            float y1 = gelu_f(C[nt][1]);
            float y2 = gelu_f(C[nt][2]);
            float y3 = gelu_f(C[nt][3]);
            __nv_bfloat16 h0, l0, h1, l1, h2, l2, h3, l3;
            split_bf16(y0, h0, l0); split_bf16(y1, h1, l1);
            split_bf16(y2, h2, l2); split_bf16(y3, h3, l3);
            __nv_bfloat162 vh0; vh0.x = h0; vh0.y = h1;
            __nv_bfloat162 vh1; vh1.x = h2; vh1.y = h3;
            __nv_bfloat162 vl0; vl0.x = l0; vl0.y = l1;
            __nv_bfloat162 vl1; vl1.x = l2; vl1.y = l3;
            *(__nv_bfloat162*)(Hh + (m0 + g) * HS + col)     = vh0;
            *(__nv_bfloat162*)(Hh + (m0 + g + 8) * HS + col) = vh1;
            *(__nv_bfloat162*)(Hl + (m0 + g) * HS + col)     = vl0;
            *(__nv_bfloat162*)(Hl + (m0 + g + 8) * HS + col) = vl1;
        }
    }
    __syncthreads();   // H complete; X reads done (Y alias safe)

    // ---------------- GEMM2: [64,128]x[128,64] ----------------
    {
        const int n0 = (warp & 3) * 16;
        float C[2][4];
#pragma unroll
        for (int nt = 0; nt < 2; nt++) {
            float bv0 = b2s[n0 + nt * 8 + 2 * tg];
            float bv1 = b2s[n0 + nt * 8 + 2 * tg + 1];
            C[nt][0] = bv0; C[nt][1] = bv1; C[nt][2] = bv0; C[nt][3] = bv1;
        }
        uint32_t aHh = smem_u32(Hh + (m0 + lrow) * HS) + akh * 16;
        uint32_t aHl = smem_u32(Hl + (m0 + lrow) * HS) + akh * 16;
        uint32_t bH = smem_u32(W2h + (n0 + bnt * 8 + brow) * W2S) + bkh * 16;
        uint32_t bL = smem_u32(W2l + (n0 + bnt * 8 + brow) * W2S) + bkh * 16;
#pragma unroll
        for (int ks = 0; ks < 8; ks++) {
            const uint32_t off = ks * 32;
            uint32_t ah0, ah1, ah2, ah3, al0, al1, al2, al3;
            ldsm4(ah0, ah1, ah2, ah3, aHh + off);
            ldsm4(al0, al1, al2, al3, aHl + off);
            uint32_t p00, p01, p10, p11;
            ldsm4(p00, p01, p10, p11, bH + off);
            uint32_t q00, q01, q10, q11;
            ldsm4(q00, q01, q10, q11, bL + off);
            mma_bf16(C[0], ah0, ah1, ah2, ah3, p00, p01);
            mma_bf16(C[0], ah0, ah1, ah2, ah3, q00, q01);
            mma_bf16(C[0], al0, al1, al2, al3, p00, p01);
            mma_bf16(C[1], ah0, ah1, ah2, ah3, p10, p11);
            mma_bf16(C[1], ah0, ah1, ah2, ah3, q10, q11);
            mma_bf16(C[1], al0, al1, al2, al3, p10, p11);
        }
#pragma unroll
        for (int nt = 0; nt < 2; nt++) {
            const int col = n0 + nt * 8 + 2 * tg;
            *(float2*)(Ys + (m0 + g) * YS + col)     = make_float2(C[nt][0], C[nt][1]);
            *(float2*)(Ys + (m0 + g + 8) * YS + col) = make_float2(C[nt][2], C[nt][3]);
        }
    }
    __syncthreads();   // Y visible to LN
}

// ---------------- edge kernel (software-pipelined gather) ----------------
__global__ __launch_bounds__(512, 1)
void edge_kernel(const float* __restrict__ ndata, const float* __restrict__ edata,
                 const int* __restrict__ src, const int* __restrict__ dst,
                 const float* __restrict__ W1, const float* __restrict__ b1,
                 const float* __restrict__ W2, const float* __restrict__ b2,
                 const float* __restrict__ gam, const float* __restrict__ bet,
                 float* __restrict__ eout, int write_out) {
    extern __shared__ char smem[];
    const int t = threadIdx.x;
    load_weights(smem, W1, b1, W2, b2, gam, bet, t);

    __nv_bfloat16* Xh = (__nv_bfloat16*)(smem + OFF_XH);
    __nv_bfloat16* Xl = (__nv_bfloat16*)(smem + OFF_XL);
    float* Ys  = (float*)(smem + OFF_XH);
    const float* gs  = (const float*)(smem + OFF_G);
    const float* bts = (const float*)(smem + OFF_BT);
    int* eidx_base = (int*)(smem + OFF_EIX);   // 2 x 128

    const int numTiles = NE / 64;  // 12500
    const int stride = gridDim.x;
    int tile = blockIdx.x;

    // prologue: indices + gather + store for first tile
    if (t < 128) {
        int e0 = tile * 64;
        eidx_base[t] = (t < 64) ? src[e0 + t] : dst[e0 + (t - 64)];
    }
    __syncthreads();   // weights + eidx visible

    float4 vals[6];
    {
        const int* eidx = eidx_base;
        int e0 = tile * 64;
#pragma unroll
        for (int j = 0; j < 6; j++) {
            int f = t + j * 512;
            int e = f / 48, p = f % 48;
            if (p < 16)
                vals[j] = *(const float4*)(ndata + (size_t)eidx[e] * DD + p * 4);
            else if (p < 32)
                vals[j] = *(const float4*)(ndata + (size_t)eidx[64 + e] * DD + (p - 16) * 4);
            else
                vals[j] = *(const float4*)(edata + (size_t)(e0 + e) * DD + (p - 32) * 4);
        }
#pragma unroll
        for (int j = 0; j < 6; j++) {
            int f = t + j * 512;
            store_x(Xh, Xl, f / 48, f % 48, vals[j]);
        }
    }

    int buf = 0;
    for (;;) {
        const int next = tile + stride;
        const bool has_next = next < numTiles;
        const int* eidx_cur = eidx_base + buf * 128;
        int* eidx_nxt = eidx_base + (buf ^ 1) * 128;

        if (has_next && t < 128) {
            int e0n = next * 64;
            eidx_nxt[t] = (t < 64) ? src[e0n + t] : dst[e0n + (t - 64)];
        }
        __syncthreads();   // X stores visible; eidx_nxt visible

        // prefetch next tile's gather into registers (overlaps with MMA below)
        if (has_next) {
            int e0n = next * 64;
#pragma unroll
            for (int j = 0; j < 6; j++) {
                int f = t + j * 512;
                int e = f / 48, p = f % 48;
                if (p < 16)
                    vals[j] = *(const float4*)(ndata + (size_t)eidx_nxt[e] * DD + p * 4);
                else if (p < 32)
                    vals[j] = *(const float4*)(ndata + (size_t)eidx_nxt[64 + e] * DD + (p - 16) * 4);
                else
                    vals[j] = *(const float4*)(edata + (size_t)(e0n + e) * DD + (p - 32) * 4);
            }
        }

        mlp_tile_tc(smem, t);

        // LayerNorm + output + scatter (16 warps x 4 rows, half-warp per row)
        {
            const int e0 = tile * 64;
            const int warp = t >> 5, lane = t & 31;
            const int half = lane >> 4, l16 = lane & 15;
#pragma unroll
            for (int it = 0; it < 2; ++it) {
                int row = warp * 4 + it * 2 + half;
                float ya[4];
                *(float4*)ya = *(const float4*)(Ys + row * YS + l16 * 4);
                float s  = ya[0] + ya[1] + ya[2] + ya[3];
                float ss = ya[0]*ya[0] + ya[1]*ya[1] + ya[2]*ya[2] + ya[3]*ya[3];
#pragma unroll
                for (int o = 8; o; o >>= 1) {
                    s  += __shfl_xor_sync(0xffffffffu, s, o);
                    ss += __shfl_xor_sync(0xffffffffu, ss, o);
                }
                float mu  = s * (1.0f / 64.0f);
                float var = ss * (1.0f / 64.0f) - mu * mu;
                float rs  = rsqrtf(var + 1e-5f);
                float o4[4];
#pragma unroll
                for (int j = 0; j < 4; j++) {
                    int c = l16 * 4 + j;
                    o4[j] = (ya[j] - mu) * rs * gs[c] + bts[c];
                }
                if (write_out)
                    *(float4*)(eout + (size_t)(e0 + row) * DD + l16 * 4) = *(float4*)o4;
                int sn = eidx_cur[row], dn = eidx_cur[64 + row];
                red_add4(g_sum_src + (size_t)sn * DD + l16 * 4, o4[0], o4[1], o4[2], o4[3]);
                red_add4(g_sum_dst + (size_t)dn * DD + l16 * 4, o4[0], o4[1], o4[2], o4[3]);
                if (l16 == 0) {
                    red_add1(g_cnt_src + sn, 1.0f);
                    red_add1(g_cnt_dst + dn, 1.0f);
                }
            }
        }

        if (!has_next) return;
        __syncthreads();   // everyone done reading Ys (X alias) + eidx_cur

#pragma unroll
        for (int j = 0; j < 6; j++) {
            int f = t + j * 512;
            store_x(Xh, Xl, f / 48, f % 48, vals[j]);
        }
        buf ^= 1;
        tile = next;
    }
}

// ---------------- node kernel ----------------
__global__ __launch_bounds__(512, 1)
void node_kernel(const float* __restrict__ ndata,
                 const float* __restrict__ W1, const float* __restrict__ b1,
                 const float* __restrict__ W2, const float* __restrict__ b2,
                 const float* __restrict__ gam, const float* __restrict__ bet,
                 float* __restrict__ nout) {
    extern __shared__ char smem[];
    const int t = threadIdx.x;
    load_weights(smem, W1, b1, W2, b2, gam, bet, t);

    __nv_bfloat16* Xh = (__nv_bfloat16*)(smem + OFF_XH);
    __nv_bfloat16* Xl = (__nv_bfloat16*)(smem + OFF_XL);
    float* Ys  = (float*)(smem + OFF_XH);
    const float* gs  = (const float*)(smem + OFF_G);
    const float* bts = (const float*)(smem + OFF_BT);
    __syncthreads();

    const int numTiles = (NN + 63) / 64;
    for (int tile = blockIdx.x; tile < numTiles; tile += gridDim.x) {
        const int n0 = tile * 64;
        for (int f = t; f < 64 * 48; f += 512) {
            int r = f / 48, p = f % 48;
            int n = n0 + r;
            float4 v = make_float4(0.f, 0.f, 0.f, 0.f);
            if (n < NN) {
                if (p < 16) {
                    float ic = 1.0f / fmaxf(g_cnt_src[n], 1.0f);
                    float4 s4 = *(const float4*)(g_sum_src + (size_t)n * DD + p * 4);
                    v = make_float4(s4.x * ic, s4.y * ic, s4.z * ic, s4.w * ic);
                } else if (p < 32) {
                    float ic = 1.0f / fmaxf(g_cnt_dst[n], 1.0f);
                    float4 s4 = *(const float4*)(g_sum_dst + (size_t)n * DD + (p - 16) * 4);
                    v = make_float4(s4.x * ic, s4.y * ic, s4.z * ic, s4.w * ic);
                } else {
                    v = *(const float4*)(ndata + (size_t)n * DD + (p - 32) * 4);
                }
            }
            store_x(Xh, Xl, r, p, v);
        }
        __syncthreads();

        mlp_tile_tc(smem, t);

        const int warp = t >> 5, lane = t & 31;
        const int half = lane >> 4, l16 = lane & 15;
#pragma unroll
        for (int it = 0; it < 2; ++it) {
            int row = warp * 4 + it * 2 + half;
            float ya[4];
            *(float4*)ya = *(const float4*)(Ys + row * YS + l16 * 4);
            float s  = ya[0] + ya[1] + ya[2] + ya[3];
            float ss = ya[0]*ya[0] + ya[1]*ya[1] + ya[2]*ya[2] + ya[3]*ya[3];
#pragma unroll
            for (int o = 8; o; o >>= 1) {
                s  += __shfl_xor_sync(0xffffffffu, s, o);
                ss += __shfl_xor_sync(0xffffffffu, ss, o);
            }
            float mu  = s * (1.0f / 64.0f);
            float var = ss * (1.0f / 64.0f) - mu * mu;
            float rs  = rsqrtf(var + 1e-5f);
            int n = n0 + row;
            if (n < NN) {
                float o4[4];
#pragma unroll
                for (int j = 0; j < 4; j++) {
                    int c = l16 * 4 + j;
                    o4[j] = (ya[j] - mu) * rs * gs[c] + bts[c];
                }
                *(float4*)(nout + (size_t)n * DD + l16 * 4) = *(float4*)o4;
            }
        }
        __syncthreads();
    }
}

// ---------------- launch ----------------
extern "C" void kernel_launch(void* const* d_in, const int* in_sizes, int n_in,
                              void* d_out, int out_size) {
    const float* ndata = (const float*)d_in[0];
    const float* edata = (const float*)d_in[1];
    const int*   src   = (const int*)d_in[2];
    const int*   dst   = (const int*)d_in[3];
    const float* eW1 = (const float*)d_in[4];
    const float* eb1 = (const float*)d_in[5];
    const float* eW2 = (const float*)d_in[6];
    const float* eb2 = (const float*)d_in[7];
    const float* eg  = (const float*)d_in[8];
    const float* ebt = (const float*)d_in[9];
    const float* nW1 = (const float*)d_in[10];
    const float* nb1 = (const float*)d_in[11];
    const float* nW2 = (const float*)d_in[12];
    const float* nb2 = (const float*)d_in[13];
    const float* ng  = (const float*)d_in[14];
    const float* nbt = (const float*)d_in[15];

    float* out  = (float*)d_out;
    float* nout = out;                        // ndata_new first
    float* eout = out + (size_t)NN * DD;      // edata_new second
    int write_edges = (out_size >= (NN + NE) * DD) ? 1 : 0;

    int sm = 148;
    cudaDeviceGetAttribute(&sm, cudaDevAttrMultiProcessorCount, 0);

    cudaFuncSetAttribute(edge_kernel, cudaFuncAttributeMaxDynamicSharedMemorySize, SMEM_BYTES);
    cudaFuncSetAttribute(node_kernel, cudaFuncAttributeMaxDynamicSharedMemorySize, SMEM_BYTES);

    // zero scratch via memset nodes (no kernel launch -> ncu -s 5 lands on edge/node kernels)
    void *p_ss, *p_sd, *p_cs, *p_cd;
    cudaGetSymbolAddress(&p_ss, g_sum_src);
    cudaGetSymbolAddress(&p_sd, g_sum_dst);
    cudaGetSymbolAddress(&p_cs, g_cnt_src);
    cudaGetSymbolAddress(&p_cd, g_cnt_dst);
    cudaMemsetAsync(p_ss, 0, (size_t)NN * DD * sizeof(float), 0);
    cudaMemsetAsync(p_sd, 0, (size_t)NN * DD * sizeof(float), 0);
    cudaMemsetAsync(p_cs, 0, (size_t)NN * sizeof(float), 0);
    cudaMemsetAsync(p_cd, 0, (size_t)NN * sizeof(float), 0);

    edge_kernel<<<sm, 512, SMEM_BYTES>>>(ndata, edata, src, dst,
                                         eW1, eb1, eW2, eb2, eg, ebt,
                                         eout, write_edges);
    node_kernel<<<sm, 512, SMEM_BYTES>>>(ndata, nW1, nb1, nW2, nb2, ng, nbt, nout);
}